// round 4
// baseline (speedup 1.0000x reference)
#include <cuda_runtime.h>
#include <stdint.h>

#define VOCAB 50257
#define KD    128
#define BM    128
#define BN    32
#define NTHR  256
#define NMT   16
#define NCOL  9
#define GRID  (NMT*NCOL)        // 144
#define NSTRIP 1571             // ceil(50257/32)

// smem (floats): A 2*128*128 = 32768 fl ; B stages 2*3*32*128 = 24576 fl
#define SBf        32768        // float offset of B region
#define SBSTAGEf   12288
#define SMEM_BYTES ((32768 + 24576) * 4)   // 229376

static __device__ __forceinline__ uint32_t smem_u32(const void* p){
    uint32_t a; asm("{ .reg .u64 t; cvta.to.shared.u64 t, %1; cvt.u32.u64 %0, t; }":"=r"(a):"l"(p)); return a;
}
static __device__ __forceinline__ uint32_t tf32r(float x){
    uint32_t u; asm("cvt.rna.tf32.f32 %0, %1;":"=r"(u):"f"(x)); return u;
}
static __device__ __forceinline__ void mma8(float* d, const uint32_t* a, const uint32_t* b){
    asm volatile("mma.sync.aligned.m16n8k8.row.col.f32.tf32.tf32.f32 "
        "{%0,%1,%2,%3}, {%4,%5,%6,%7}, {%8,%9}, {%0,%1,%2,%3};"
        : "+f"(d[0]),"+f"(d[1]),"+f"(d[2]),"+f"(d[3])
        : "r"(a[0]),"r"(a[1]),"r"(a[2]),"r"(a[3]),"r"(b[0]),"r"(b[1]));
}
#define CPA(dst,src) asm volatile("cp.async.cg.shared.global [%0], [%1], 16;"::"r"(dst),"l"(src):"memory")
#define CPCOMMIT()   asm volatile("cp.async.commit_group;":::"memory")
#define CPWAIT1()    asm volatile("cp.async.wait_group 1;":::"memory")
#define CPWAIT0()    asm volatile("cp.async.wait_group 0;":::"memory")

__global__ void __launch_bounds__(NTHR,1) idec_kernel(
    const float* __restrict__ pr, const float* __restrict__ pi,
    const float* __restrict__ br, const float* __restrict__ bi,
    const float* __restrict__ W,  const float* __restrict__ bb,
    float* __restrict__ out)
{
    extern __shared__ float smem[];
    const uint32_t sbase = smem_u32(smem);
    const int tid  = threadIdx.x;
    const int lane = tid & 31, wid = tid >> 5;
    const int mtile = blockIdx.x % NMT;
    const int cgp   = blockIdx.x / NMT;
    const int s0 = (cgp * NSTRIP) / NCOL;
    const int s1 = ((cgp + 1) * NSTRIP) / NCOL;

    // ---- load A (pr, pi) once: tf32-rounded, XOR-swizzled ----
    {
        const float* g0 = pr + (size_t)mtile * BM * KD;
        const float* g1 = pi + (size_t)mtile * BM * KD;
        for (int i = tid; i < BM * 32; i += NTHR){
            int row = i >> 5, c4 = (i & 31) << 2;
            int cs  = c4 ^ ((row & 7) << 2);
            float4 v = *(const float4*)(g0 + row * KD + c4);
            *(uint4*)(smem + row * KD + cs) =
                make_uint4(tf32r(v.x), tf32r(v.y), tf32r(v.z), tf32r(v.w));
            float4 w4 = *(const float4*)(g1 + row * KD + c4);
            *(uint4*)(smem + 16384 + row * KD + cs) =
                make_uint4(tf32r(w4.x), tf32r(w4.y), tf32r(w4.z), tf32r(w4.w));
        }
    }

    const float* Bsrc[3] = {br, bi, W};
    auto issueB = [&](int s, int stage){
        const int v0 = s * BN;
        const uint32_t dstBase = sbase + (SBf + stage * SBSTAGEf) * 4;
        for (int i = tid; i < 3 * BN * 32; i += NTHR){   // 12 chunks/thread
            int mat = i >> 10, r = (i >> 5) & 31, c4 = (i & 31) << 2;
            int vr = v0 + r; if (vr > VOCAB - 1) vr = VOCAB - 1;
            int cs = c4 ^ ((r & 7) << 2);
            CPA(dstBase + (uint32_t)(mat * 4096 + r * KD + cs) * 4,
                Bsrc[mat] + (size_t)vr * KD + c4);
        }
        CPCOMMIT();
    };

    issueB(s0, 0);

    const int wm = wid & 3, wn = wid >> 2;     // warp grid 4(M) x 2(N), tile 32x16
    const int lq = lane >> 2, lr = lane & 3;
    const int swz = lq << 2;

    for (int s = s0; s < s1; s++){
        const int stage = (s - s0) & 1;
        if (s + 1 < s1){ issueB(s + 1, stage ^ 1); CPWAIT1(); }
        else           { CPWAIT0(); }
        __syncthreads();

        const float* sB = smem + SBf + stage * SBSTAGEf;

        float cRE[2][2][4] = {}, cIM[2][2][4] = {}, cLN[2][2][4] = {};

        #pragma unroll
        for (int k16 = 0; k16 < 16; k16++){
            const int k0 = k16 * 8;
            const int ko0 = (k0 + lr)     ^ swz;
            const int ko1 = (k0 + lr + 4) ^ swz;

            uint32_t apr[2][4], api[2][4];
            #pragma unroll
            for (int mt = 0; mt < 2; mt++){
                const int rb = (wm * 32 + mt * 16 + lq) * KD;
                apr[mt][0] = __float_as_uint(smem[rb + ko0]);
                apr[mt][1] = __float_as_uint(smem[rb + 1024 + ko0]);
                apr[mt][2] = __float_as_uint(smem[rb + ko1]);
                apr[mt][3] = __float_as_uint(smem[rb + 1024 + ko1]);
                api[mt][0] = __float_as_uint(smem[16384 + rb + ko0]);
                api[mt][1] = __float_as_uint(smem[16384 + rb + 1024 + ko0]);
                api[mt][2] = __float_as_uint(smem[16384 + rb + ko1]);
                api[mt][3] = __float_as_uint(smem[16384 + rb + 1024 + ko1]);
            }
            uint32_t bf[3][2][2], brn[2][2];
            #pragma unroll
            for (int nt = 0; nt < 2; nt++){
                const int nb = (wn * 16 + nt * 8 + lq) * KD;
                #pragma unroll
                for (int mat = 0; mat < 3; mat++){
                    bf[mat][nt][0] = tf32r(sB[mat * 4096 + nb + ko0]);
                    bf[mat][nt][1] = tf32r(sB[mat * 4096 + nb + ko1]);
                }
                brn[nt][0] = bf[0][nt][0] ^ 0x80000000u;
                brn[nt][1] = bf[0][nt][1] ^ 0x80000000u;
            }
            #pragma unroll
            for (int mt = 0; mt < 2; mt++)
            #pragma unroll
            for (int nt = 0; nt < 2; nt++){
                mma8(cRE[mt][nt], apr[mt], bf[0][nt]);   // pr.br
                mma8(cRE[mt][nt], api[mt], bf[1][nt]);   // pi.bi
                mma8(cIM[mt][nt], apr[mt], bf[1][nt]);   // pr.bi
                mma8(cIM[mt][nt], api[mt], brn[nt]);     // -pi.br
                mma8(cLN[mt][nt], apr[mt], bf[2][nt]);   // pr.W
            }
        }
        __syncthreads();   // stage buffer free before next-next cp.async

        // ---- epilogue: out = RE^2 + IM^2 + LIN + b ----
        const int v0 = s * BN;
        #pragma unroll
        for (int mt = 0; mt < 2; mt++){
            const int r0 = mtile * BM + wm * 32 + mt * 16 + lq;
            #pragma unroll
            for (int nt = 0; nt < 2; nt++){
                const int c0 = v0 + wn * 16 + nt * 8 + (lr << 1);
                #pragma unroll
                for (int j = 0; j < 4; j++){
                    const int row = r0 + (j >> 1) * 8;
                    const int col = c0 + (j & 1);
                    if (col < VOCAB){
                        float re = cRE[mt][nt][j], im = cIM[mt][nt][j];
                        out[(size_t)row * VOCAB + col] =
                            fmaf(re, re, fmaf(im, im, cLN[mt][nt][j] + __ldg(bb + col)));
                    }
                }
            }
        }
    }
}

extern "C" void kernel_launch(void* const* d_in, const int* in_sizes, int n_in,
                              void* d_out, int out_size)
{
    cudaFuncSetAttribute(idec_kernel, cudaFuncAttributeMaxDynamicSharedMemorySize, SMEM_BYTES);
    idec_kernel<<<GRID, NTHR, SMEM_BYTES>>>(
        (const float*)d_in[0], (const float*)d_in[1],
        (const float*)d_in[2], (const float*)d_in[3],
        (const float*)d_in[4], (const float*)d_in[5],
        (float*)d_out);
}

// round 5
// speedup vs baseline: 1.0352x; 1.0352x over previous
#include <cuda_runtime.h>
#include <stdint.h>

#define VOCAB  50257
#define NSTRIP 786              // strips of 64 vocab rows
#define NGRP   (NSTRIP*4)       // 16-row groups = 3144
#define MATF   (NGRP*2048)      // floats per mat in scratch (6,438,912)
#define NMT    16
#define TT     (NMT*NSTRIP)     // 12576 total (mtile,strip) units
#define GRID   148
#define NTHR   256
#define SMEM_BYTES ((32768+24576)*4)   // A 128KB + B 2x48KB = 229376

__device__ float g_scratch[3ull*MATF];   // rounded+fragment-permuted br,bi,W

static __device__ __forceinline__ uint32_t smem_u32(const void* p){
    uint32_t a; asm("{ .reg .u64 t; cvta.to.shared.u64 t, %1; cvt.u32.u64 %0, t; }":"=r"(a):"l"(p)); return a;
}
static __device__ __forceinline__ uint32_t tf32r(float x){
    uint32_t u; asm("cvt.rna.tf32.f32 %0, %1;":"=r"(u):"f"(x)); return u;
}
static __device__ __forceinline__ void mma8(float* d, const uint4& a, uint32_t b0, uint32_t b1){
    asm volatile("mma.sync.aligned.m16n8k8.row.col.f32.tf32.tf32.f32 "
        "{%0,%1,%2,%3}, {%4,%5,%6,%7}, {%8,%9}, {%0,%1,%2,%3};"
        : "+f"(d[0]),"+f"(d[1]),"+f"(d[2]),"+f"(d[3])
        : "r"(a.x),"r"(a.y),"r"(a.z),"r"(a.w),"r"(b0),"r"(b1));
}
#define CPA(dst,src) asm volatile("cp.async.cg.shared.global [%0], [%1], 16;"::"r"(dst),"l"(src):"memory")
#define CPCOMMIT()   asm volatile("cp.async.commit_group;":::"memory")
#define CPWAIT1()    asm volatile("cp.async.wait_group 1;":::"memory")
#define CPWAIT0()    asm volatile("cp.async.wait_group 0;":::"memory")

// ---- prep: round to tf32 (rna) + permute B mats into fragment-chunk order ----
// chunk(mat,G,k16,lane): {P[G*16+lq][k], P[..][k+4], P[G*16+8+lq][k], P[..][k+4]},
// lq=lane>>2, lr=lane&3, k=k16*8+lr  -> one LDS.128 = B frags for a 16-wide n pair
__global__ void __launch_bounds__(256) prep_kernel(
    const float* __restrict__ br, const float* __restrict__ bi, const float* __restrict__ W)
{
    unsigned i = blockIdx.x*256u + threadIdx.x;
    unsigned lane = i & 31u, k16 = (i>>5)&15u, gm = i>>9;
    unsigned mat = gm / NGRP, G = gm - mat*NGRP;
    const float* src = (mat==0) ? br : ((mat==1) ? bi : W);
    int lq = lane>>2, lr = lane&3, k = k16*8+lr;
    int r0 = G*16 + lq;     if (r0 > VOCAB-1) r0 = VOCAB-1;
    int r1 = G*16 + 8 + lq; if (r1 > VOCAB-1) r1 = VOCAB-1;
    uint4 u;
    u.x = tf32r(src[(size_t)r0*128 + k]);
    u.y = tf32r(src[(size_t)r0*128 + k + 4]);
    u.z = tf32r(src[(size_t)r1*128 + k]);
    u.w = tf32r(src[(size_t)r1*128 + k + 4]);
    *(uint4*)&g_scratch[(size_t)mat*MATF + ((size_t)(G*16u + k16)*32u + lane)*4u] = u;
}

// ---- main: persistent, A frag-resident in smem, B streamed in k-half buffers ----
__global__ void __launch_bounds__(NTHR,1) idec_main(
    const float* __restrict__ pr, const float* __restrict__ pi,
    const float* __restrict__ bb, float* __restrict__ out)
{
    extern __shared__ float sm[];
    const uint32_t sbase = smem_u32(sm);
    const int tid = threadIdx.x, lane = tid&31, wid = tid>>5;
    const int wm = wid&3, wn = wid>>2;          // warp grid 4(M) x 2(N), tile 32x32
    const int lq = lane>>2, lr = lane&3;

    const int t0 = (int)(((long long)blockIdx.x     * TT) / GRID);
    const int t1 = (int)(((long long)(blockIdx.x+1) * TT) / GRID);

    float cRE[2][4][4], cIM[2][4][4], cLN[2][4][4];
    #pragma unroll
    for (int a=0;a<2;a++)
    #pragma unroll
    for (int n=0;n<4;n++)
    #pragma unroll
    for (int j=0;j<4;j++){ cRE[a][n][j]=0.f; cIM[a][n][j]=0.f; cLN[a][n][j]=0.f; }

    auto issue_half = [&](int ss, int kh, bool pred){
        if (pred){
            #pragma unroll
            for (int ii = 0; ii < 12; ii++){
                int i = tid + ii*NTHR;
                int ln = i&31, ng = (i>>5)&3, kr = (i>>7)&7, mat = i>>10;
                const float* src = &g_scratch[(size_t)mat*MATF
                    + ((size_t)(unsigned)((ss*4+ng)*16 + kh*8 + kr)*32u + (unsigned)ln)*4u];
                uint32_t dst = sbase + (32768u + (uint32_t)kh*12288u + (uint32_t)mat*4096u
                    + (uint32_t)((kr*4+ng)*32+ln)*4u)*4u;
                CPA(dst, src);
            }
        }
        CPCOMMIT();
    };

    auto mma_half = [&](int kh){
        const float* sB = sm + 32768 + kh*12288;
        #pragma unroll
        for (int kr = 0; kr < 8; kr++){
            const int k16 = kh*8 + kr;
            uint4 apr[2], api[2];
            #pragma unroll
            for (int mt=0; mt<2; mt++){
                apr[mt] = *(const uint4*)&sm[        ((wm*2+mt)*16 + k16)*128 + lane*4];
                api[mt] = *(const uint4*)&sm[16384 + ((wm*2+mt)*16 + k16)*128 + lane*4];
            }
            uint4 fbr[2], fbi[2], fww[2];
            #pragma unroll
            for (int c=0;c<2;c++){
                const int off = ((kr*4 + wn*2 + c)*32 + lane)*4;
                fbr[c] = *(const uint4*)&sB[       off];
                fbi[c] = *(const uint4*)&sB[4096 + off];
                fww[c] = *(const uint4*)&sB[8192 + off];
            }
            #pragma unroll
            for (int mt=0; mt<2; mt++)
            #pragma unroll
            for (int c=0;c<2;c++){
                mma8(cRE[mt][c*2+0], apr[mt], fbr[c].x, fbr[c].y);
                mma8(cRE[mt][c*2+1], apr[mt], fbr[c].z, fbr[c].w);
            }
            #pragma unroll
            for (int mt=0; mt<2; mt++)
            #pragma unroll
            for (int c=0;c<2;c++){
                mma8(cIM[mt][c*2+0], apr[mt], fbi[c].x, fbi[c].y);
                mma8(cIM[mt][c*2+1], apr[mt], fbi[c].z, fbi[c].w);
            }
            #pragma unroll
            for (int mt=0; mt<2; mt++)
            #pragma unroll
            for (int c=0;c<2;c++){
                mma8(cLN[mt][c*2+0], apr[mt], fww[c].x, fww[c].y);
                mma8(cLN[mt][c*2+1], apr[mt], fww[c].z, fww[c].w);
            }
            #pragma unroll
            for (int c=0;c<2;c++){   // negate br for IM -= pi*br
                fbr[c].x ^= 0x80000000u; fbr[c].y ^= 0x80000000u;
                fbr[c].z ^= 0x80000000u; fbr[c].w ^= 0x80000000u;
            }
            #pragma unroll
            for (int mt=0; mt<2; mt++)
            #pragma unroll
            for (int c=0;c<2;c++){
                mma8(cIM[mt][c*2+0], api[mt], fbr[c].x, fbr[c].y);
                mma8(cIM[mt][c*2+1], api[mt], fbr[c].z, fbr[c].w);
            }
            #pragma unroll
            for (int mt=0; mt<2; mt++)
            #pragma unroll
            for (int c=0;c<2;c++){
                mma8(cRE[mt][c*2+0], api[mt], fbi[c].x, fbi[c].y);
                mma8(cRE[mt][c*2+1], api[mt], fbi[c].z, fbi[c].w);
            }
        }
    };

    int t = t0;
    while (t < t1){
        const int mtile = t / NSTRIP;
        int s = t - mtile*NSTRIP;
        int send = s + (t1 - t); if (send > NSTRIP) send = NSTRIP;
        t = mtile*NSTRIP + send;

        // load A (pr,pi) into fragment-order smem, tf32-rounded
        for (int i = tid; i < 8192; i += NTHR){
            int ln = i&31, kk = (i>>5)&15, g = (i>>9)&7, m = i>>12;
            int lql = ln>>2, lrl = ln&3, k = kk*8 + lrl;
            const float* src = m ? pi : pr;
            size_t rb = ((size_t)mtile*128 + g*16 + lql)*128;
            uint4 u;
            u.x = tf32r(src[rb + k]);
            u.y = tf32r(src[rb + 8*128 + k]);
            u.z = tf32r(src[rb + k + 4]);
            u.w = tf32r(src[rb + 8*128 + k + 4]);
            *(uint4*)&sm[m*16384 + (g*16+kk)*128 + ln*4] = u;
        }

        issue_half(s, 0, true);
        issue_half(s, 1, true);

        for (; s < send; s++){
            const bool nxt = (s+1 < send);
            // k-half 0
            CPWAIT1(); __syncthreads();
            mma_half(0);
            __syncthreads();
            issue_half(s+1, 0, nxt);
            // k-half 1
            CPWAIT1(); __syncthreads();
            mma_half(1);
            __syncthreads();
            issue_half(s+1, 1, nxt);

            // epilogue: out = RE^2 + IM^2 + LIN + b ; reset accs
            const int colbase = s*64 + wn*32 + lr*2;
            #pragma unroll
            for (int n=0; n<4; n++){
                const int cb = colbase + (n>>1)*16 + (n&1)*8;
                #pragma unroll
                for (int p=0; p<2; p++){
                    const int col = cb + p;
                    if (col < VOCAB){
                        const float bv = __ldg(bb + col);
                        #pragma unroll
                        for (int mt=0; mt<2; mt++){
                            const int row = mtile*128 + wm*32 + mt*16 + lq;
                            float re = cRE[mt][n][p],   im = cIM[mt][n][p];
                            out[(size_t)row*VOCAB + col] =
                                fmaf(re,re, fmaf(im,im, cLN[mt][n][p] + bv));
                            re = cRE[mt][n][p+2]; im = cIM[mt][n][p+2];
                            out[(size_t)(row+8)*VOCAB + col] =
                                fmaf(re,re, fmaf(im,im, cLN[mt][n][p+2] + bv));
                        }
                    }
                }
            }
            #pragma unroll
            for (int a=0;a<2;a++)
            #pragma unroll
            for (int n=0;n<4;n++)
            #pragma unroll
            for (int j=0;j<4;j++){ cRE[a][n][j]=0.f; cIM[a][n][j]=0.f; cLN[a][n][j]=0.f; }
        }
        CPWAIT0(); __syncthreads();
    }
}

extern "C" void kernel_launch(void* const* d_in, const int* in_sizes, int n_in,
                              void* d_out, int out_size)
{
    const float* pr = (const float*)d_in[0];
    const float* pi = (const float*)d_in[1];
    const float* br = (const float*)d_in[2];
    const float* bi = (const float*)d_in[3];
    const float* W  = (const float*)d_in[4];
    const float* bb = (const float*)d_in[5];

    prep_kernel<<<3*NGRP*2, 256>>>(br, bi, W);   // 18864 blocks, exact cover
    cudaFuncSetAttribute(idec_main, cudaFuncAttributeMaxDynamicSharedMemorySize, SMEM_BYTES);
    idec_main<<<GRID, NTHR, SMEM_BYTES>>>(pr, pi, bb, (float*)d_out);
}

// round 6
// speedup vs baseline: 1.4071x; 1.3593x over previous
#include <cuda_runtime.h>
#include <cuda_fp16.h>
#include <stdint.h>

#define VOCAB  50257
#define NSTRIP 786
#define NMT    16
#define TT     (NMT*NSTRIP)
#define GRID   148
#define NTHR   256
#define MATH   6438912ull          // halves per B mat: 786*8192
#define SMEM_BYTES 229376          // A 3*32KB + B 2*64KB

__device__ __half g_scr[4ull*MATH];   // br, bi, br+bi, W  (fragment-permuted fp16)

static __device__ __forceinline__ uint32_t smem_u32(const void* p){
    uint32_t a; asm("{ .reg .u64 t; cvta.to.shared.u64 t, %1; cvt.u32.u64 %0, t; }":"=r"(a):"l"(p)); return a;
}
static __device__ __forceinline__ uint32_t h2(float lo, float hi){
    __half2 h = __floats2half2_rn(lo, hi);
    return *(uint32_t*)&h;
}
static __device__ __forceinline__ void mma16(float* d, const uint4& a, uint32_t b0, uint32_t b1){
    asm volatile("mma.sync.aligned.m16n8k16.row.col.f32.f16.f16.f32 "
        "{%0,%1,%2,%3}, {%4,%5,%6,%7}, {%8,%9}, {%0,%1,%2,%3};"
        : "+f"(d[0]),"+f"(d[1]),"+f"(d[2]),"+f"(d[3])
        : "r"(a.x),"r"(a.y),"r"(a.z),"r"(a.w),"r"(b0),"r"(b1));
}
#define CPA(dst,src) asm volatile("cp.async.cg.shared.global [%0], [%1], 16;"::"r"(dst),"l"(src):"memory")
#define CPCOMMIT()   asm volatile("cp.async.commit_group;":::"memory")
#define CPWAIT1()    asm volatile("cp.async.wait_group 1;":::"memory")
#define CPWAIT0()    asm volatile("cp.async.wait_group 0;":::"memory")

// ---- prep: build fp16 fragment-chunk scratch for br, bi, br+bi, W ----
// chunk(mat,s,pg,kk,lane) = uint4 {b0,b1 of n-tile pg*16, b0,b1 of n-tile pg*16+8}
__global__ void __launch_bounds__(256) prep_kernel(
    const float* __restrict__ br, const float* __restrict__ bi, const float* __restrict__ W)
{
    unsigned i = blockIdx.x*256u + threadIdx.x;
    unsigned ln = i & 31u, pg = (i>>5)&3u, kk = (i>>7)&7u, q = i>>10;
    unsigned mat = q / 786u, s = q - mat*786u;
    int lq = ln>>2, lr = ln&3, k0 = kk*16 + lr*2;
    int rr0 = s*64 + pg*16 + lq;  if (rr0 > VOCAB-1) rr0 = VOCAB-1;
    int rr1 = s*64 + pg*16 + 8 + lq; if (rr1 > VOCAB-1) rr1 = VOCAB-1;
    float2 a0,a1,a2,a3;
    if (mat == 2){
        float2 x0 = *(const float2*)(br + (size_t)rr0*128 + k0);
        float2 y0 = *(const float2*)(bi + (size_t)rr0*128 + k0);
        float2 x1 = *(const float2*)(br + (size_t)rr0*128 + k0 + 8);
        float2 y1 = *(const float2*)(bi + (size_t)rr0*128 + k0 + 8);
        float2 x2 = *(const float2*)(br + (size_t)rr1*128 + k0);
        float2 y2 = *(const float2*)(bi + (size_t)rr1*128 + k0);
        float2 x3 = *(const float2*)(br + (size_t)rr1*128 + k0 + 8);
        float2 y3 = *(const float2*)(bi + (size_t)rr1*128 + k0 + 8);
        a0 = make_float2(x0.x+y0.x, x0.y+y0.y);
        a1 = make_float2(x1.x+y1.x, x1.y+y1.y);
        a2 = make_float2(x2.x+y2.x, x2.y+y2.y);
        a3 = make_float2(x3.x+y3.x, x3.y+y3.y);
    } else {
        const float* src = (mat==0) ? br : ((mat==1) ? bi : W);
        a0 = *(const float2*)(src + (size_t)rr0*128 + k0);
        a1 = *(const float2*)(src + (size_t)rr0*128 + k0 + 8);
        a2 = *(const float2*)(src + (size_t)rr1*128 + k0);
        a3 = *(const float2*)(src + (size_t)rr1*128 + k0 + 8);
    }
    uint4 u;
    u.x = h2(a0.x, a0.y);   // tile0 b0 (k-low)
    u.y = h2(a1.x, a1.y);   // tile0 b1 (k-high)
    u.z = h2(a2.x, a2.y);   // tile1 b0
    u.w = h2(a3.x, a3.y);   // tile1 b1
    *(uint4*)&g_scr[(size_t)mat*MATH + (size_t)s*8192 + (size_t)((kk*4+pg)*32+ln)*8] = u;
}

__global__ void __launch_bounds__(NTHR,1) idec_main(
    const float* __restrict__ pr, const float* __restrict__ pi,
    const float* __restrict__ bb, float* __restrict__ out)
{
    extern __shared__ __align__(16) char smraw[];
    __half* smh = (__half*)smraw;
    const uint32_t sbase = smem_u32(smraw);
    const int tid = threadIdx.x, lane = tid&31, wid = tid>>5;
    const int wm = wid&3, wn = wid>>2;          // 4(M) x 2(N) warps, tile 32x32
    const int lq = lane>>2, lr = lane&3;

    const int t0 = (int)(((long long)blockIdx.x     * TT) / GRID);
    const int t1 = (int)(((long long)(blockIdx.x+1) * TT) / GRID);

    float c1[2][4][4], c2[2][4][4], c3[2][4][4], cL[2][4][4];
    #pragma unroll
    for (int a=0;a<2;a++)
    #pragma unroll
    for (int n=0;n<4;n++)
    #pragma unroll
    for (int j=0;j<4;j++){ c1[a][n][j]=0.f; c2[a][n][j]=0.f; c3[a][n][j]=0.f; cL[a][n][j]=0.f; }

    auto issueB = [&](int ss, int st){
        #pragma unroll
        for (int ii=0; ii<16; ii++){
            int i = tid + ii*NTHR;
            int ln = i&31, kk=(i>>5)&7, pg=(i>>8)&3, mb=i>>10;
            const __half* src = &g_scr[(size_t)mb*MATH + (size_t)ss*8192
                                       + (size_t)((kk*4+pg)*32+ln)*8];
            uint32_t dst = sbase + 98304u + (uint32_t)st*65536u + (uint32_t)mb*16384u
                         + (uint32_t)((kk*4+pg)*32+ln)*16u;
            CPA(dst, src);
        }
        CPCOMMIT();
    };

    auto mma_strip = [&](int st){
        const int bbase = 49152 + st*32768;   // halves
        #pragma unroll
        for (int kk=0; kk<8; kk++){
            uint4 fpr[2], fpi[2], fpd[2];
            #pragma unroll
            for (int mt=0; mt<2; mt++){
                const int off = (((wm*2+mt)*8+kk)*32+lane)*8;
                fpr[mt] = *(const uint4*)&smh[off];
                fpi[mt] = *(const uint4*)&smh[16384+off];
                fpd[mt] = *(const uint4*)&smh[32768+off];
            }
            uint4 f1[2], f2[2], f3[2], fw[2];
            #pragma unroll
            for (int c=0;c<2;c++){
                const int off = bbase + ((kk*4 + wn*2 + c)*32 + lane)*8;
                f1[c] = *(const uint4*)&smh[off];
                f2[c] = *(const uint4*)&smh[off+8192];
                f3[c] = *(const uint4*)&smh[off+16384];
                fw[c] = *(const uint4*)&smh[off+24576];
            }
            #pragma unroll
            for (int mt=0; mt<2; mt++)
            #pragma unroll
            for (int c=0;c<2;c++){
                mma16(c1[mt][c*2+0], fpr[mt], f1[c].x, f1[c].y);
                mma16(c1[mt][c*2+1], fpr[mt], f1[c].z, f1[c].w);
            }
            #pragma unroll
            for (int mt=0; mt<2; mt++)
            #pragma unroll
            for (int c=0;c<2;c++){
                mma16(c2[mt][c*2+0], fpi[mt], f2[c].x, f2[c].y);
                mma16(c2[mt][c*2+1], fpi[mt], f2[c].z, f2[c].w);
            }
            #pragma unroll
            for (int mt=0; mt<2; mt++)
            #pragma unroll
            for (int c=0;c<2;c++){
                mma16(c3[mt][c*2+0], fpd[mt], f3[c].x, f3[c].y);
                mma16(c3[mt][c*2+1], fpd[mt], f3[c].z, f3[c].w);
            }
            #pragma unroll
            for (int mt=0; mt<2; mt++)
            #pragma unroll
            for (int c=0;c<2;c++){
                mma16(cL[mt][c*2+0], fpr[mt], fw[c].x, fw[c].y);
                mma16(cL[mt][c*2+1], fpr[mt], fw[c].z, fw[c].w);
            }
        }
    };

    int t = t0;
    while (t < t1){
        const int mtile = t / NSTRIP;
        int s = t - mtile*NSTRIP;
        int send = s + (t1 - t); if (send > NSTRIP) send = NSTRIP;
        t = mtile*NSTRIP + send;

        // ---- load A mats (pr, pi, pr-pi) as fp16 fragment chunks ----
        for (int i = tid; i < 6144; i += NTHR){
            int ln=i&31, kk=(i>>5)&7, g=(i>>8)&7, m=i>>11;
            int lql=ln>>2, lrl=ln&3, k0=kk*16+lrl*2;
            size_t r0 = ((size_t)mtile*128 + g*16 + lql)*128;
            size_t r1 = r0 + 8*128;
            uint4 u;
            if (m == 2){
                float2 x0=*(const float2*)(pr+r0+k0),   y0=*(const float2*)(pi+r0+k0);
                float2 x1=*(const float2*)(pr+r1+k0),   y1=*(const float2*)(pi+r1+k0);
                float2 x2=*(const float2*)(pr+r0+k0+8), y2=*(const float2*)(pi+r0+k0+8);
                float2 x3=*(const float2*)(pr+r1+k0+8), y3=*(const float2*)(pi+r1+k0+8);
                u.x = h2(x0.x-y0.x, x0.y-y0.y);   // a0: row lq, k-low
                u.y = h2(x1.x-y1.x, x1.y-y1.y);   // a1: row lq+8, k-low
                u.z = h2(x2.x-y2.x, x2.y-y2.y);   // a2: row lq, k-high
                u.w = h2(x3.x-y3.x, x3.y-y3.y);   // a3: row lq+8, k-high
            } else {
                const float* src = m ? pi : pr;
                float2 v0=*(const float2*)(src+r0+k0);
                float2 v1=*(const float2*)(src+r1+k0);
                float2 v2=*(const float2*)(src+r0+k0+8);
                float2 v3=*(const float2*)(src+r1+k0+8);
                u.x = h2(v0.x,v0.y); u.y = h2(v1.x,v1.y);
                u.z = h2(v2.x,v2.y); u.w = h2(v3.x,v3.y);
            }
            *(uint4*)&smh[m*16384 + ((g*8+kk)*32+ln)*8] = u;
        }

        int st = 0;
        issueB(s, 0);
        for (; s < send; s++){
            const bool nxt = (s+1 < send);
            if (nxt){ issueB(s+1, st^1); CPWAIT1(); }
            else    { CPWAIT0(); }
            __syncthreads();
            mma_strip(st);
            __syncthreads();

            // ---- epilogue: RE=m1+m2, IM=m3-m1+m2 ; out = RE^2+IM^2+LIN+b ----
            const int colbase = s*64 + wn*32 + lr*2;
            #pragma unroll
            for (int n=0; n<4; n++){
                const int cb = colbase + (n>>1)*16 + (n&1)*8;
                #pragma unroll
                for (int p=0; p<2; p++){
                    const int col = cb + p;
                    if (col < VOCAB){
                        const float bv = __ldg(bb + col);
                        #pragma unroll
                        for (int mt=0; mt<2; mt++){
                            const int row = mtile*128 + wm*32 + mt*16 + lq;
                            float m1=c1[mt][n][p], m2=c2[mt][n][p], m3=c3[mt][n][p];
                            float re = m1+m2, im = m3-m1+m2;
                            out[(size_t)row*VOCAB + col] =
                                fmaf(re,re, fmaf(im,im, cL[mt][n][p] + bv));
                            m1=c1[mt][n][p+2]; m2=c2[mt][n][p+2]; m3=c3[mt][n][p+2];
                            re = m1+m2; im = m3-m1+m2;
                            out[(size_t)(row+8)*VOCAB + col] =
                                fmaf(re,re, fmaf(im,im, cL[mt][n][p+2] + bv));
                        }
                    }
                }
            }
            #pragma unroll
            for (int a=0;a<2;a++)
            #pragma unroll
            for (int n=0;n<4;n++)
            #pragma unroll
            for (int j=0;j<4;j++){ c1[a][n][j]=0.f; c2[a][n][j]=0.f; c3[a][n][j]=0.f; cL[a][n][j]=0.f; }
            st ^= 1;
        }
    }
}

extern "C" void kernel_launch(void* const* d_in, const int* in_sizes, int n_in,
                              void* d_out, int out_size)
{
    const float* pr = (const float*)d_in[0];
    const float* pi = (const float*)d_in[1];
    const float* br = (const float*)d_in[2];
    const float* bi = (const float*)d_in[3];
    const float* W  = (const float*)d_in[4];
    const float* bb = (const float*)d_in[5];

    prep_kernel<<<12576, 256>>>(br, bi, W);
    cudaFuncSetAttribute(idec_main, cudaFuncAttributeMaxDynamicSharedMemorySize, SMEM_BYTES);
    idec_main<<<GRID, NTHR, SMEM_BYTES>>>(pr, pi, bb, (float*)d_out);
}

// round 8
// speedup vs baseline: 1.6707x; 1.1873x over previous
#include <cuda_runtime.h>
#include <cuda_fp16.h>
#include <stdint.h>

#define VOCAB  50257
#define NSTRIP 786
#define NMT    16
#define TT     (NMT*NSTRIP)
#define GRID   148
#define NTHR   512
#define MATH   6438912ull            // halves per B mat: 786*8192
#define SMEM_BYTES ((32768 + 3*24576)*2)   // A 64KB + B 3x48KB = 212992

__device__ __half g_scr[3ull*MATH];  // br, bi, W (fragment-permuted fp16)

static __device__ __forceinline__ uint32_t smem_u32(const void* p){
    uint32_t a; asm("{ .reg .u64 t; cvta.to.shared.u64 t, %1; cvt.u32.u64 %0, t; }":"=r"(a):"l"(p)); return a;
}
static __device__ __forceinline__ uint32_t h2(float lo, float hi){
    __half2 h = __floats2half2_rn(lo, hi);
    return *(uint32_t*)&h;
}
static __device__ __forceinline__ uint32_t hsub2(uint32_t a, uint32_t b){
    uint32_t r; asm("sub.rn.f16x2 %0,%1,%2;":"=r"(r):"r"(a),"r"(b)); return r;
}
static __device__ __forceinline__ uint32_t hadd2(uint32_t a, uint32_t b){
    uint32_t r; asm("add.rn.f16x2 %0,%1,%2;":"=r"(r):"r"(a),"r"(b)); return r;
}
static __device__ __forceinline__ void mma16(float* d, const uint4& a, uint32_t b0, uint32_t b1){
    asm volatile("mma.sync.aligned.m16n8k16.row.col.f32.f16.f16.f32 "
        "{%0,%1,%2,%3}, {%4,%5,%6,%7}, {%8,%9}, {%0,%1,%2,%3};"
        : "+f"(d[0]),"+f"(d[1]),"+f"(d[2]),"+f"(d[3])
        : "r"(a.x),"r"(a.y),"r"(a.z),"r"(a.w),"r"(b0),"r"(b1));
}
#define CPA(dst,src) asm volatile("cp.async.cg.shared.global [%0], [%1], 16;"::"r"(dst),"l"(src):"memory")
#define CPCOMMIT()   asm volatile("cp.async.commit_group;":::"memory")
#define CPWAIT2()    asm volatile("cp.async.wait_group 2;":::"memory")
#define CPWAIT0()    asm volatile("cp.async.wait_group 0;":::"memory")

// ---- prep: fp16 fragment-chunk scratch for br, bi, W ----
__global__ void __launch_bounds__(256) prep_kernel(
    const float* __restrict__ br, const float* __restrict__ bi, const float* __restrict__ W)
{
    unsigned i = blockIdx.x*256u + threadIdx.x;
    unsigned ln = i & 31u, pg = (i>>5)&3u, kk = (i>>7)&7u, q = i>>10;
    unsigned mat = q / 786u, s = q - mat*786u;
    const float* src = (mat==0) ? br : ((mat==1) ? bi : W);
    int lq = ln>>2, lr = ln&3, k0 = kk*16 + lr*2;
    int r0 = s*64 + pg*16 + lq;     if (r0 > VOCAB-1) r0 = VOCAB-1;
    int r1 = s*64 + pg*16 + 8 + lq; if (r1 > VOCAB-1) r1 = VOCAB-1;
    float2 a0 = *(const float2*)(src + (size_t)r0*128 + k0);
    float2 a1 = *(const float2*)(src + (size_t)r0*128 + k0 + 8);
    float2 a2 = *(const float2*)(src + (size_t)r1*128 + k0);
    float2 a3 = *(const float2*)(src + (size_t)r1*128 + k0 + 8);
    uint4 u;
    u.x = h2(a0.x, a0.y);   // n-tile0 b0 (row lq,  k-low)
    u.y = h2(a1.x, a1.y);   // n-tile0 b1 (row lq,  k-high)
    u.z = h2(a2.x, a2.y);   // n-tile1 b0 (row lq+8, k-low)
    u.w = h2(a3.x, a3.y);   // n-tile1 b1 (row lq+8, k-high)
    *(uint4*)&g_scr[(size_t)mat*MATH + (size_t)s*8192 + (size_t)((kk*4+pg)*32+ln)*8] = u;
}

__global__ void __launch_bounds__(NTHR,1) idec_main(
    const float* __restrict__ pr, const float* __restrict__ pi,
    const float* __restrict__ bb, float* __restrict__ out)
{
    extern __shared__ __align__(16) char smraw[];
    __half* smh = (__half*)smraw;
    const uint32_t sbase = smem_u32(smraw);
    const int tid = threadIdx.x, lane = tid&31, wid = tid>>5;
    const int wm = wid&3, wn = wid>>2;          // 4(M) x 4(N) warps, tile 32x16
    const int lq = lane>>2, lr = lane&3;

    const int t0 = (int)(((long long)blockIdx.x     * TT) / GRID);
    const int t1 = (int)(((long long)(blockIdx.x+1) * TT) / GRID);

    float c1[2][2][4], c2[2][2][4], c3[2][2][4], cL[2][2][4];
    #pragma unroll
    for (int a=0;a<2;a++)
    #pragma unroll
    for (int n=0;n<2;n++)
    #pragma unroll
    for (int j=0;j<4;j++){ c1[a][n][j]=0.f; c2[a][n][j]=0.f; c3[a][n][j]=0.f; cL[a][n][j]=0.f; }

    auto issueB = [&](int ss, int st){
        #pragma unroll
        for (int ii=0; ii<6; ii++){
            int i = tid + ii*NTHR;
            int ln = i&31, kk=(i>>5)&7, pg=(i>>8)&3, mb=i>>10;
            const __half* src = &g_scr[(size_t)mb*MATH + (size_t)ss*8192
                                       + (size_t)((kk*4+pg)*32+ln)*8];
            uint32_t dst = sbase + (uint32_t)(32768 + st*24576 + mb*8192
                         + ((kk*4+pg)*32+ln)*8)*2u;
            CPA(dst, src);
        }
        CPCOMMIT();
    };

    auto mma_strip = [&](int st){
        const int bbase = 32768 + st*24576;
        #pragma unroll
        for (int kk=0; kk<8; kk++){
            uint4 fpr[2], fpi[2];
            #pragma unroll
            for (int mt=0; mt<2; mt++){
                const int off = (((wm*2+mt)*8+kk)*32+lane)*8;
                fpr[mt] = *(const uint4*)&smh[off];
                fpi[mt] = *(const uint4*)&smh[16384+off];
            }
            const int boff = bbase + ((kk*4 + wn)*32 + lane)*8;
            uint4 f1 = *(const uint4*)&smh[boff];
            uint4 f2 = *(const uint4*)&smh[boff+8192];
            uint4 fw = *(const uint4*)&smh[boff+16384];
            // derived operands
            uint4 fpd[2], f3;
            #pragma unroll
            for (int mt=0; mt<2; mt++){
                fpd[mt].x = hsub2(fpr[mt].x, fpi[mt].x);
                fpd[mt].y = hsub2(fpr[mt].y, fpi[mt].y);
                fpd[mt].z = hsub2(fpr[mt].z, fpi[mt].z);
                fpd[mt].w = hsub2(fpr[mt].w, fpi[mt].w);
            }
            f3.x = hadd2(f1.x, f2.x); f3.y = hadd2(f1.y, f2.y);
            f3.z = hadd2(f1.z, f2.z); f3.w = hadd2(f1.w, f2.w);
            #pragma unroll
            for (int mt=0; mt<2; mt++){
                mma16(c1[mt][0], fpr[mt], f1.x, f1.y);
                mma16(c1[mt][1], fpr[mt], f1.z, f1.w);
                mma16(c2[mt][0], fpi[mt], f2.x, f2.y);
                mma16(c2[mt][1], fpi[mt], f2.z, f2.w);
                mma16(cL[mt][0], fpr[mt], fw.x, fw.y);
                mma16(cL[mt][1], fpr[mt], fw.z, fw.w);
                mma16(c3[mt][0], fpd[mt], f3.x, f3.y);
                mma16(c3[mt][1], fpd[mt], f3.z, f3.w);
            }
        }
    };

    int t = t0;
    while (t < t1){
        const int mtile = t / NSTRIP;
        int s = t - mtile*NSTRIP;
        const int sb = s;
        int send = s + (t1 - t); if (send > NSTRIP) send = NSTRIP;
        t = mtile*NSTRIP + send;

        __syncthreads();
        CPWAIT0();                 // drain stale prefetches before stage reuse

        // ---- load A (pr, pi) as fp16 fragment chunks ----
        // A-fragment reg order: {(r,klo),(r+8,klo),(r,khi),(r+8,khi)}
        for (int i = tid; i < 4096; i += NTHR){
            int ln=i&31, kk=(i>>5)&7, g=(i>>8)&7, m=i>>11;
            int lql=ln>>2, lrl=ln&3, k0=kk*16+lrl*2;
            const float* src = m ? pi : pr;
            size_t r0 = ((size_t)mtile*128 + g*16 + lql)*128;
            size_t r1 = r0 + 8*128;
            float2 v0=*(const float2*)(src+r0+k0);      // (r,   klo)
            float2 v1=*(const float2*)(src+r1+k0);      // (r+8, klo)
            float2 v2=*(const float2*)(src+r0+k0+8);    // (r,   khi)
            float2 v3=*(const float2*)(src+r1+k0+8);    // (r+8, khi)
            uint4 u;
            u.x = h2(v0.x,v0.y); u.y = h2(v1.x,v1.y);
            u.z = h2(v2.x,v2.y); u.w = h2(v3.x,v3.y);
            *(uint4*)&smh[m*16384 + ((g*8+kk)*32+ln)*8] = u;
        }

        issueB(sb, 0);
        issueB(min(sb+1, NSTRIP-1), 1);

        for (; s < send; s++){
            const int st = (s - sb) % 3;
            __syncthreads();                       // stage (st+2)%3 consumers done
            issueB(min(s+2, NSTRIP-1), (st+2)%3);
            CPWAIT2();                             // group for stage st complete
            __syncthreads();
            mma_strip(st);

            // ---- epilogue: RE=m1+m2, IM=m3-m1+m2 ; out = RE^2+IM^2+LIN+b ----
            const int colbase = s*64 + wn*16 + lr*2;
            #pragma unroll
            for (int n=0; n<2; n++){
                const int cb = colbase + n*8;
                #pragma unroll
                for (int p=0; p<2; p++){
                    const int col = cb + p;
                    if (col < VOCAB){
                        const float bv = __ldg(bb + col);
                        #pragma unroll
                        for (int mt=0; mt<2; mt++){
                            const int row = mtile*128 + wm*32 + mt*16 + lq;
                            float m1=c1[mt][n][p], m2=c2[mt][n][p], m3=c3[mt][n][p];
                            float re = m1+m2, im = m3-m1+m2;
                            out[(size_t)row*VOCAB + col] =
                                fmaf(re,re, fmaf(im,im, cL[mt][n][p] + bv));
                            m1=c1[mt][n][p+2]; m2=c2[mt][n][p+2]; m3=c3[mt][n][p+2];
                            re = m1+m2; im = m3-m1+m2;
                            out[(size_t)(row+8)*VOCAB + col] =
                                fmaf(re,re, fmaf(im,im, cL[mt][n][p+2] + bv));
                        }
                    }
                }
            }
            #pragma unroll
            for (int a=0;a<2;a++)
            #pragma unroll
            for (int n=0;n<2;n++)
            #pragma unroll
            for (int j=0;j<4;j++){ c1[a][n][j]=0.f; c2[a][n][j]=0.f; c3[a][n][j]=0.f; cL[a][n][j]=0.f; }
        }
    }
}

extern "C" void kernel_launch(void* const* d_in, const int* in_sizes, int n_in,
                              void* d_out, int out_size)
{
    const float* pr = (const float*)d_in[0];
    const float* pi = (const float*)d_in[1];
    const float* br = (const float*)d_in[2];
    const float* bi = (const float*)d_in[3];
    const float* W  = (const float*)d_in[4];
    const float* bb = (const float*)d_in[5];

    prep_kernel<<<9432, 256>>>(br, bi, W);   // 3*786*4 blocks
    cudaFuncSetAttribute(idec_main, cudaFuncAttributeMaxDynamicSharedMemorySize, SMEM_BYTES);
    idec_main<<<GRID, NTHR, SMEM_BYTES>>>(pr, pi, bb, (float*)d_out);
}

// round 9
// speedup vs baseline: 1.9667x; 1.1772x over previous
#include <cuda_runtime.h>
#include <cuda_fp16.h>
#include <stdint.h>

#define VOCAB  50257
#define NSTRIP 786
#define NMT    16
#define TT     (NMT*NSTRIP)
#define GRID   148
#define NTHR   512
#define MATH   6438912ull            // halves per B mat: 786*8192
#define STG_OFF 163840               // byte offset of staging (after A 64KB + B 2x48KB)
#define SMEM_BYTES (STG_OFF + 128*72*4)   // 200704

__device__ __half g_scr[3ull*MATH];  // br, bi, W (fragment-permuted fp16)

static __device__ __forceinline__ uint32_t smem_u32(const void* p){
    uint32_t a; asm("{ .reg .u64 t; cvta.to.shared.u64 t, %1; cvt.u32.u64 %0, t; }":"=r"(a):"l"(p)); return a;
}
static __device__ __forceinline__ uint32_t h2(float lo, float hi){
    __half2 h = __floats2half2_rn(lo, hi);
    return *(uint32_t*)&h;
}
static __device__ __forceinline__ uint32_t hsub2(uint32_t a, uint32_t b){
    uint32_t r; asm("sub.rn.f16x2 %0,%1,%2;":"=r"(r):"r"(a),"r"(b)); return r;
}
static __device__ __forceinline__ uint32_t hadd2(uint32_t a, uint32_t b){
    uint32_t r; asm("add.rn.f16x2 %0,%1,%2;":"=r"(r):"r"(a),"r"(b)); return r;
}
static __device__ __forceinline__ void mma16(float* d, const uint4& a, uint32_t b0, uint32_t b1){
    asm volatile("mma.sync.aligned.m16n8k16.row.col.f32.f16.f16.f32 "
        "{%0,%1,%2,%3}, {%4,%5,%6,%7}, {%8,%9}, {%0,%1,%2,%3};"
        : "+f"(d[0]),"+f"(d[1]),"+f"(d[2]),"+f"(d[3])
        : "r"(a.x),"r"(a.y),"r"(a.z),"r"(a.w),"r"(b0),"r"(b1));
}
#define CPA(dst,src) asm volatile("cp.async.cg.shared.global [%0], [%1], 16;"::"r"(dst),"l"(src):"memory")
#define CPCOMMIT()   asm volatile("cp.async.commit_group;":::"memory")
#define CPWAIT1()    asm volatile("cp.async.wait_group 1;":::"memory")
#define CPWAIT0()    asm volatile("cp.async.wait_group 0;":::"memory")

// ---- prep: fp16 fragment-chunk scratch for br, bi, W ----
__global__ void __launch_bounds__(256) prep_kernel(
    const float* __restrict__ br, const float* __restrict__ bi, const float* __restrict__ W)
{
    unsigned i = blockIdx.x*256u + threadIdx.x;
    unsigned ln = i & 31u, pg = (i>>5)&3u, kk = (i>>7)&7u, q = i>>10;
    unsigned mat = q / 786u, s = q - mat*786u;
    const float* src = (mat==0) ? br : ((mat==1) ? bi : W);
    int lq = ln>>2, lr = ln&3, k0 = kk*16 + lr*2;
    int r0 = s*64 + pg*16 + lq;     if (r0 > VOCAB-1) r0 = VOCAB-1;
    int r1 = s*64 + pg*16 + 8 + lq; if (r1 > VOCAB-1) r1 = VOCAB-1;
    float2 a0 = *(const float2*)(src + (size_t)r0*128 + k0);
    float2 a1 = *(const float2*)(src + (size_t)r0*128 + k0 + 8);
    float2 a2 = *(const float2*)(src + (size_t)r1*128 + k0);
    float2 a3 = *(const float2*)(src + (size_t)r1*128 + k0 + 8);
    uint4 u;
    u.x = h2(a0.x, a0.y);
    u.y = h2(a1.x, a1.y);
    u.z = h2(a2.x, a2.y);
    u.w = h2(a3.x, a3.y);
    *(uint4*)&g_scr[(size_t)mat*MATH + (size_t)s*8192 + (size_t)((kk*4+pg)*32+ln)*8] = u;
}

__global__ void __launch_bounds__(NTHR,1) idec_main(
    const float* __restrict__ pr, const float* __restrict__ pi,
    const float* __restrict__ bb, float* __restrict__ out)
{
    extern __shared__ __align__(16) char smraw[];
    __half* smh = (__half*)smraw;
    float*  stg = (float*)(smraw + STG_OFF);
    const uint32_t sbase = smem_u32(smraw);
    const int tid = threadIdx.x, lane = tid&31, wid = tid>>5;
    const int wm = wid&3, wn = wid>>2;          // 4(M) x 4(N) warps, tile 32x16
    const int lq = lane>>2, lr = lane&3;

    const int t0 = (int)(((long long)blockIdx.x     * TT) / GRID);
    const int t1 = (int)(((long long)(blockIdx.x+1) * TT) / GRID);

    float c1[2][2][4], c2[2][2][4], c3[2][2][4], cL[2][2][4];
    #pragma unroll
    for (int a=0;a<2;a++)
    #pragma unroll
    for (int n=0;n<2;n++)
    #pragma unroll
    for (int j=0;j<4;j++){ c1[a][n][j]=0.f; c2[a][n][j]=0.f; c3[a][n][j]=0.f; cL[a][n][j]=0.f; }

    auto issueB = [&](int ss, int st){
        #pragma unroll
        for (int ii=0; ii<6; ii++){
            int i = tid + ii*NTHR;
            int ln = i&31, kk=(i>>5)&7, pg=(i>>8)&3, mb=i>>10;
            const __half* src = &g_scr[(size_t)mb*MATH + (size_t)ss*8192
                                       + (size_t)((kk*4+pg)*32+ln)*8];
            uint32_t dst = sbase + (uint32_t)(32768 + st*24576 + mb*8192
                         + ((kk*4+pg)*32+ln)*8)*2u;
            CPA(dst, src);
        }
        CPCOMMIT();
    };

    auto mma_strip = [&](int st){
        const int bbase = 32768 + st*24576;
        #pragma unroll
        for (int kk=0; kk<8; kk++){
            uint4 fpr[2], fpi[2];
            #pragma unroll
            for (int mt=0; mt<2; mt++){
                const int off = (((wm*2+mt)*8+kk)*32+lane)*8;
                fpr[mt] = *(const uint4*)&smh[off];
                fpi[mt] = *(const uint4*)&smh[16384+off];
            }
            const int boff = bbase + ((kk*4 + wn)*32 + lane)*8;
            uint4 f1 = *(const uint4*)&smh[boff];
            uint4 f2 = *(const uint4*)&smh[boff+8192];
            uint4 fw = *(const uint4*)&smh[boff+16384];
            uint4 fpd[2], f3;
            #pragma unroll
            for (int mt=0; mt<2; mt++){
                fpd[mt].x = hsub2(fpr[mt].x, fpi[mt].x);
                fpd[mt].y = hsub2(fpr[mt].y, fpi[mt].y);
                fpd[mt].z = hsub2(fpr[mt].z, fpi[mt].z);
                fpd[mt].w = hsub2(fpr[mt].w, fpi[mt].w);
            }
            f3.x = hadd2(f1.x, f2.x); f3.y = hadd2(f1.y, f2.y);
            f3.z = hadd2(f1.z, f2.z); f3.w = hadd2(f1.w, f2.w);
            #pragma unroll
            for (int mt=0; mt<2; mt++){
                mma16(c1[mt][0], fpr[mt], f1.x, f1.y);
                mma16(c1[mt][1], fpr[mt], f1.z, f1.w);
                mma16(c2[mt][0], fpi[mt], f2.x, f2.y);
                mma16(c2[mt][1], fpi[mt], f2.z, f2.w);
                mma16(cL[mt][0], fpr[mt], fw.x, fw.y);
                mma16(cL[mt][1], fpr[mt], fw.z, fw.w);
                mma16(c3[mt][0], fpd[mt], f3.x, f3.y);
                mma16(c3[mt][1], fpd[mt], f3.z, f3.w);
            }
        }
    };

    int t = t0;
    while (t < t1){
        const int mtile = t / NSTRIP;
        int s = t - mtile*NSTRIP;
        const int sb = s;
        int send = s + (t1 - t); if (send > NSTRIP) send = NSTRIP;
        t = mtile*NSTRIP + send;

        __syncthreads();
        CPWAIT0();                 // drain stale prefetches before stage reuse

        // ---- load A (pr, pi) as fp16 fragment chunks ----
        for (int i = tid; i < 4096; i += NTHR){
            int ln=i&31, kk=(i>>5)&7, g=(i>>8)&7, m=i>>11;
            int lql=ln>>2, lrl=ln&3, k0=kk*16+lrl*2;
            const float* src = m ? pi : pr;
            size_t r0 = ((size_t)mtile*128 + g*16 + lql)*128;
            size_t r1 = r0 + 8*128;
            float2 v0=*(const float2*)(src+r0+k0);
            float2 v1=*(const float2*)(src+r1+k0);
            float2 v2=*(const float2*)(src+r0+k0+8);
            float2 v3=*(const float2*)(src+r1+k0+8);
            uint4 u;
            u.x = h2(v0.x,v0.y); u.y = h2(v1.x,v1.y);
            u.z = h2(v2.x,v2.y); u.w = h2(v3.x,v3.y);
            *(uint4*)&smh[m*16384 + ((g*8+kk)*32+ln)*8] = u;
        }

        issueB(sb, 0);

        for (; s < send; s++){
            const int st = (s - sb) & 1;
            const bool nxt = (s+1 < send);
            if (nxt){ issueB(s+1, st^1); CPWAIT1(); }
            else    { CPWAIT0(); }
            __syncthreads();                 // B stage st ready; prev staging read done
            mma_strip(st);

            // ---- stage RE^2+IM^2+LIN into padded smem tile ----
            {
                const int colb = wn*16 + lr*2;
                #pragma unroll
                for (int n=0; n<2; n++){
                    #pragma unroll
                    for (int p=0; p<2; p++){
                        const int col = colb + n*8 + p;
                        #pragma unroll
                        for (int mt=0; mt<2; mt++){
                            const int row = wm*32 + mt*16 + lq;
                            float m1=c1[mt][n][p], m2=c2[mt][n][p], m3=c3[mt][n][p];
                            float re = m1+m2, im = m3-m1+m2;
                            stg[row*72 + col] = fmaf(re,re, fmaf(im,im, cL[mt][n][p]));
                            m1=c1[mt][n][p+2]; m2=c2[mt][n][p+2]; m3=c3[mt][n][p+2];
                            re = m1+m2; im = m3-m1+m2;
                            stg[(row+8)*72 + col] = fmaf(re,re, fmaf(im,im, cL[mt][n][p+2]));
                        }
                    }
                }
            }
            __syncthreads();                 // staging complete; B stage st consumed

            // ---- coalesced sweep: smem -> gmem (+bias) ----
            {
                const size_t rbase = (size_t)mtile*128;
                #pragma unroll
                for (int it=0; it<16; it++){
                    int i = tid + it*NTHR;
                    int row = i>>6, col = i&63;
                    int gcol = s*64 + col;
                    if (gcol < VOCAB)
                        out[(rbase+row)*VOCAB + gcol] = stg[row*72 + col] + __ldg(bb + gcol);
                }
            }

            #pragma unroll
            for (int a=0;a<2;a++)
            #pragma unroll
            for (int n=0;n<2;n++)
            #pragma unroll
            for (int j=0;j<4;j++){ c1[a][n][j]=0.f; c2[a][n][j]=0.f; c3[a][n][j]=0.f; cL[a][n][j]=0.f; }
        }
    }
}

extern "C" void kernel_launch(void* const* d_in, const int* in_sizes, int n_in,
                              void* d_out, int out_size)
{
    const float* pr = (const float*)d_in[0];
    const float* pi = (const float*)d_in[1];
    const float* br = (const float*)d_in[2];
    const float* bi = (const float*)d_in[3];
    const float* W  = (const float*)d_in[4];
    const float* bb = (const float*)d_in[5];

    prep_kernel<<<9432, 256>>>(br, bi, W);
    cudaFuncSetAttribute(idec_main, cudaFuncAttributeMaxDynamicSharedMemorySize, SMEM_BYTES);
    idec_main<<<GRID, NTHR, SMEM_BYTES>>>(pr, pi, bb, (float*)d_out);
}